// round 3
// baseline (speedup 1.0000x reference)
#include <cuda_runtime.h>
#include <math.h>
#include <stdint.h>

#define NN 50000
#define DD 128
#define EE 800000
#define FULL 0xffffffffu

// ---------------- scratch (device globals; no allocation) ----------------
__device__ __align__(16) float g_hs0[NN * DD];
__device__ __align__(16) float g_hs1[NN * DD];
__device__ __align__(16) float g_hfood[NN * DD];
__device__ __align__(16) float g_hnut[NN * DD];
__device__ __align__(16) float g_as0[NN * 4];
__device__ __align__(16) float g_as1[NN * 4];
__device__ __align__(16) float g_ad0[NN * 4];
__device__ __align__(16) float g_ad1[NN * 4];
__device__ __align__(16) float g_Ad0[DD * 4];
__device__ __align__(16) float g_Ad1[DD * 4];
__device__ int g_off0[NN + 1];
__device__ int g_off1[NN + 1];
__device__ int g_cur0[NN];
__device__ int g_cur1[NN];
__device__ int g_csr0[EE];
__device__ int g_csr1[EE];

__device__ __forceinline__ float lrelu(float x) { return x > 0.f ? x : 0.2f * x; }
__device__ __forceinline__ float eluf(float x) { return x > 0.f ? x : expm1f(x); }

__device__ __forceinline__ uint32_t f2tf32(float x) {
    uint32_t r;
    asm("cvt.rna.tf32.f32 %0, %1;" : "=r"(r) : "f"(x));
    return r;
}

#define MMA_TF32(c, a0, a1, a2, a3, b0, b1)                                   \
    asm volatile(                                                             \
        "mma.sync.aligned.m16n8k8.row.col.f32.tf32.tf32.f32 "                 \
        "{%0,%1,%2,%3}, {%4,%5,%6,%7}, {%8,%9}, {%0,%1,%2,%3};"               \
        : "+f"(c[0]), "+f"(c[1]), "+f"(c[2]), "+f"(c[3])                      \
        : "r"(a0), "r"(a1), "r"(a2), "r"(a3), "r"(b0), "r"(b1))

// ---------------- tensor-core GEMM (3xTF32 split) + alpha_s epilogue ---------
// Y[N,128] = X[N,128] @ W[128,128];  AS[n,h] = sum_c Y[n,h*32+c]*att[h*32+c]
// block: 256 threads = 8 warps; tile 128 rows x 128 cols; warp = 16 rows.
// grid: (391, 2) -- blockIdx.y selects relation.
__global__ __launch_bounds__(256) void gemm_tc(
    const float* __restrict__ X0, const float* __restrict__ X1,
    const float* __restrict__ W0, const float* __restrict__ W1,
    const float* __restrict__ att0, const float* __restrict__ att1,
    float* __restrict__ Y0, float* __restrict__ Y1,
    float* __restrict__ AS0, float* __restrict__ AS1) {
    int rel = blockIdx.y;
    const float* __restrict__ X   = rel ? X1 : X0;
    const float* __restrict__ W   = rel ? W1 : W0;
    const float* __restrict__ att = rel ? att1 : att0;
    float* __restrict__ Y  = rel ? Y1 : Y0;
    float* __restrict__ AS = rel ? AS1 : AS0;

    // Xh/Xl: k-major, padded to 132 words for conflict-free A-frag loads.
    __shared__ uint32_t Xh[16][132];
    __shared__ uint32_t Xl[16][132];
    // W fragments in native mma layout: [s(k8 substep)][ntile][lane*2 + part]
    __shared__ uint32_t Wh[2][16][64];
    __shared__ uint32_t Wl[2][16][64];
    __shared__ float att_s[128];

    int tid = threadIdx.x;
    int lane = tid & 31, warp = tid >> 5;
    int rowBase = blockIdx.x * 128;
    int wr = warp * 16;

    if (tid < 128) att_s[tid] = att[tid];

    float acc[16][4];
#pragma unroll
    for (int t = 0; t < 16; t++) {
        acc[t][0] = 0.f; acc[t][1] = 0.f; acc[t][2] = 0.f; acc[t][3] = 0.f;
    }

    // loader indexing
    int xrow = tid & 127;
    int xkh  = (tid >> 7) * 8;  // 0 or 8
    int grow = rowBase + xrow;
    bool xv = grow < NN;
    const float* Xb = X + (size_t)grow * DD;
    int wk = tid >> 4;          // 0..15 (k within step)
    int wt = tid & 15;          // n-tile
    int ws = wk >> 3;           // k8 substep
    int wpart = (wk >> 2) & 1;  // b0 vs b1
    int wk3 = wk & 3;

#pragma unroll
    for (int k0 = 0; k0 < 128; k0 += 16) {
        float4 a0 = xv ? *(const float4*)(Xb + k0 + xkh) : make_float4(0.f, 0.f, 0.f, 0.f);
        float4 a1 = xv ? *(const float4*)(Xb + k0 + xkh + 4) : make_float4(0.f, 0.f, 0.f, 0.f);
        float4 b0 = *(const float4*)(W + (size_t)(k0 + wk) * DD + wt * 8);
        float4 b1 = *(const float4*)(W + (size_t)(k0 + wk) * DD + wt * 8 + 4);
        __syncthreads();
        {
            float xs[8] = {a0.x, a0.y, a0.z, a0.w, a1.x, a1.y, a1.z, a1.w};
#pragma unroll
            for (int j = 0; j < 8; j++) {
                int k = xkh + j;
                uint32_t h = f2tf32(xs[j]);
                Xh[k][xrow] = h;
                Xl[k][xrow] = f2tf32(xs[j] - __uint_as_float(h));
            }
            float wsv[8] = {b0.x, b0.y, b0.z, b0.w, b1.x, b1.y, b1.z, b1.w};
#pragma unroll
            for (int j = 0; j < 8; j++) {
                int ln = wk3 | (j << 2);
                uint32_t h = f2tf32(wsv[j]);
                Wh[ws][wt][ln * 2 + wpart] = h;
                Wl[ws][wt][ln * 2 + wpart] = f2tf32(wsv[j] - __uint_as_float(h));
            }
        }
        __syncthreads();
#pragma unroll
        for (int s = 0; s < 2; s++) {
            int k = 8 * s + (lane & 3);
            int r = wr + (lane >> 2);
            uint32_t ah0 = Xh[k][r],     ah1 = Xh[k][r + 8];
            uint32_t ah2 = Xh[k + 4][r], ah3 = Xh[k + 4][r + 8];
            uint32_t al0 = Xl[k][r],     al1 = Xl[k][r + 8];
            uint32_t al2 = Xl[k + 4][r], al3 = Xl[k + 4][r + 8];
#pragma unroll
            for (int t = 0; t < 16; t++) {
                uint32_t bh0 = Wh[s][t][lane * 2], bh1 = Wh[s][t][lane * 2 + 1];
                uint32_t bl0 = Wl[s][t][lane * 2], bl1 = Wl[s][t][lane * 2 + 1];
                MMA_TF32(acc[t], ah0, ah1, ah2, ah3, bh0, bh1);
                MMA_TF32(acc[t], ah0, ah1, ah2, ah3, bl0, bl1);
                MMA_TF32(acc[t], al0, al1, al2, al3, bh0, bh1);
            }
        }
    }

    // epilogue: Y store + fused alpha_s
    int tig = lane & 3, g = lane >> 2;
#pragma unroll
    for (int rs = 0; rs < 2; rs++) {
        int gr = rowBase + wr + g + rs * 8;
        float h0 = 0.f, h1 = 0.f, h2 = 0.f, h3 = 0.f;
#pragma unroll
        for (int t = 0; t < 16; t++) {
            float c0 = acc[t][rs * 2], c1 = acc[t][rs * 2 + 1];
            float va = att_s[8 * t + 2 * tig], vb = att_s[8 * t + 2 * tig + 1];
            float p = c0 * va + c1 * vb;
            if (t < 4) h0 += p;
            else if (t < 8) h1 += p;
            else if (t < 12) h2 += p;
            else h3 += p;
            if (gr < NN)
                *(float2*)(Y + (size_t)gr * DD + 8 * t + 2 * tig) = make_float2(c0, c1);
        }
        h0 += __shfl_xor_sync(FULL, h0, 1); h0 += __shfl_xor_sync(FULL, h0, 2);
        h1 += __shfl_xor_sync(FULL, h1, 1); h1 += __shfl_xor_sync(FULL, h1, 2);
        h2 += __shfl_xor_sync(FULL, h2, 1); h2 += __shfl_xor_sync(FULL, h2, 2);
        h3 += __shfl_xor_sync(FULL, h3, 1); h3 += __shfl_xor_sync(FULL, h3, 2);
        if (tig == 0 && gr < NN)
            *(float4*)(AS + (size_t)gr * 4) = make_float4(h0, h1, h2, h3);
    }
}

// ---------------- Avec: Ad[d,h] = sum_c Wdst[d, h*32+c] * att[h,c] ----------------
__global__ void avec2(const float* __restrict__ Wd0, const float* __restrict__ Wd1,
                      const float* __restrict__ at0, const float* __restrict__ at1,
                      float* __restrict__ Ad0, float* __restrict__ Ad1) {
    int rel = blockIdx.x;
    const float* W = rel ? Wd1 : Wd0;
    const float* att = rel ? at1 : at0;
    float* out = rel ? Ad1 : Ad0;
    int d = threadIdx.x;
#pragma unroll
    for (int hh = 0; hh < 4; hh++) {
        float s = 0.f;
#pragma unroll
        for (int c = 0; c < 32; c++) s += W[d * 128 + hh * 32 + c] * att[hh * 32 + c];
        out[d * 4 + hh] = s;
    }
}

// ---------------- alpha_d[n,h] = xd[n,:] @ Ad[:,h] (warp per node) ----------------
__global__ __launch_bounds__(256) void alpha2(const float* __restrict__ xd0,
                                              const float* __restrict__ xd1,
                                              const float* __restrict__ Ad0,
                                              const float* __restrict__ Ad1,
                                              float* __restrict__ out0,
                                              float* __restrict__ out1) {
    int rel = blockIdx.y;
    const float* x = rel ? xd1 : xd0;
    const float* avec = rel ? Ad1 : Ad0;
    float* alpha = rel ? out1 : out0;
    int wid = (blockIdx.x * blockDim.x + threadIdx.x) >> 5;
    int lane = threadIdx.x & 31;
    if (wid >= NN) return;
    float p0 = 0.f, p1 = 0.f, p2 = 0.f, p3 = 0.f;
#pragma unroll
    for (int j = 0; j < 4; j++) {
        int d = lane + j * 32;
        float xv = x[(size_t)wid * DD + d];
        float4 av = *(const float4*)(avec + d * 4);
        p0 += xv * av.x; p1 += xv * av.y; p2 += xv * av.z; p3 += xv * av.w;
    }
#pragma unroll
    for (int o = 16; o; o >>= 1) {
        p0 += __shfl_xor_sync(FULL, p0, o);
        p1 += __shfl_xor_sync(FULL, p1, o);
        p2 += __shfl_xor_sync(FULL, p2, o);
        p3 += __shfl_xor_sync(FULL, p3, o);
    }
    if (lane == 0) *(float4*)(alpha + (size_t)wid * 4) = make_float4(p0, p1, p2, p3);
}

// ---------------- CSR build (fused over both relations) ----------------
__global__ void zero2(int* __restrict__ a, int* __restrict__ b, int n) {
    for (int i = blockIdx.x * blockDim.x + threadIdx.x; i < n; i += gridDim.x * blockDim.x) {
        a[i] = 0; b[i] = 0;
    }
}
__global__ void hist2(const int* __restrict__ d0, const int* __restrict__ d1,
                      int* __restrict__ c0, int* __restrict__ c1, int n) {
    for (int i = blockIdx.x * blockDim.x + threadIdx.x; i < n; i += gridDim.x * blockDim.x) {
        atomicAdd(&c0[d0[i] + 1], 1);
        atomicAdd(&c1[d1[i] + 1], 1);
    }
}
__global__ __launch_bounds__(1024) void scan2(int* __restrict__ a0, int* __restrict__ a1, int n) {
    int* a = blockIdx.x ? a1 : a0;
    __shared__ int warpsum[32];
    __shared__ int carry_s;
    int tid = threadIdx.x, lane = tid & 31, w = tid >> 5;
    if (tid == 0) carry_s = 0;
    __syncthreads();
    for (int base = 0; base < n; base += 1024) {
        int idx = base + tid;
        int v = (idx < n) ? a[idx] : 0;
        int x = v;
#pragma unroll
        for (int o = 1; o < 32; o <<= 1) {
            int t = __shfl_up_sync(FULL, x, o);
            if (lane >= o) x += t;
        }
        if (lane == 31) warpsum[w] = x;
        __syncthreads();
        if (w == 0) {
            int y = warpsum[lane];
#pragma unroll
            for (int o = 1; o < 32; o <<= 1) {
                int t = __shfl_up_sync(FULL, y, o);
                if (lane >= o) y += t;
            }
            warpsum[lane] = y;
        }
        __syncthreads();
        int incl = x + (w > 0 ? warpsum[w - 1] : 0);
        int carry = carry_s;
        if (idx < n) a[idx] = carry + incl;
        __syncthreads();
        if (tid == 1023) carry_s = carry + warpsum[31];
        __syncthreads();
    }
}
__global__ void copy2(const int* __restrict__ o0, const int* __restrict__ o1,
                      int* __restrict__ c0, int* __restrict__ c1, int n) {
    for (int i = blockIdx.x * blockDim.x + threadIdx.x; i < n; i += gridDim.x * blockDim.x) {
        c0[i] = o0[i]; c1[i] = o1[i];
    }
}
__global__ void fill2(const int* __restrict__ e0, const int* __restrict__ e1,
                      int* __restrict__ cu0, int* __restrict__ cu1,
                      int* __restrict__ cs0, int* __restrict__ cs1, int n) {
    for (int i = blockIdx.x * blockDim.x + threadIdx.x; i < n; i += gridDim.x * blockDim.x) {
        int p0 = atomicAdd(&cu0[e0[n + i]], 1);
        cs0[p0] = e0[i];
        int p1 = atomicAdd(&cu1[e1[n + i]], 1);
        cs1[p1] = e1[i];
    }
}

// ---------------- GAT aggregation (both relations) + ELU epilogue ----------------
__global__ __launch_bounds__(256) void gat_aggregate2(
    const float* __restrict__ hsA, const float* __restrict__ asA,
    const float* __restrict__ adA, const int* __restrict__ offA,
    const int* __restrict__ csrA, const float* __restrict__ bA, float* __restrict__ oA,
    const float* __restrict__ hsB, const float* __restrict__ asB,
    const float* __restrict__ adB, const int* __restrict__ offB,
    const int* __restrict__ csrB, const float* __restrict__ bB, float* __restrict__ oB) {
    int gwid = (blockIdx.x * blockDim.x + threadIdx.x) >> 5;
    if (gwid >= 2 * NN) return;
    int rel = gwid >= NN;
    int wid = gwid - rel * NN;
    int lane = threadIdx.x & 31;
    const float* __restrict__ hs      = rel ? hsB : hsA;
    const float* __restrict__ alpha_s = rel ? asB : asA;
    const float* __restrict__ alpha_d = rel ? adB : adA;
    const int* __restrict__ off       = rel ? offB : offA;
    const int* __restrict__ csr       = rel ? csrB : csrA;
    const float* __restrict__ bias    = rel ? bB : bA;
    float* __restrict__ out           = rel ? oB : oA;

    int s = off[wid], e = off[wid + 1];
    float4 ad = *(const float4*)(alpha_d + (size_t)wid * 4);

    float m0 = -3e38f, m1 = -3e38f, m2 = -3e38f, m3 = -3e38f;
    for (int i = s + lane; i < e; i += 32) {
        int src = csr[i];
        float4 as = *(const float4*)(alpha_s + (size_t)src * 4);
        m0 = fmaxf(m0, lrelu(as.x + ad.x));
        m1 = fmaxf(m1, lrelu(as.y + ad.y));
        m2 = fmaxf(m2, lrelu(as.z + ad.z));
        m3 = fmaxf(m3, lrelu(as.w + ad.w));
    }
#pragma unroll
    for (int o = 16; o; o >>= 1) {
        m0 = fmaxf(m0, __shfl_xor_sync(FULL, m0, o));
        m1 = fmaxf(m1, __shfl_xor_sync(FULL, m1, o));
        m2 = fmaxf(m2, __shfl_xor_sync(FULL, m2, o));
        m3 = fmaxf(m3, __shfl_xor_sync(FULL, m3, o));
    }
    float s0 = 0.f, s1 = 0.f, s2 = 0.f, s3 = 0.f;
    for (int i = s + lane; i < e; i += 32) {
        int src = csr[i];
        float4 as = *(const float4*)(alpha_s + (size_t)src * 4);
        s0 += __expf(lrelu(as.x + ad.x) - m0);
        s1 += __expf(lrelu(as.y + ad.y) - m1);
        s2 += __expf(lrelu(as.z + ad.z) - m2);
        s3 += __expf(lrelu(as.w + ad.w) - m3);
    }
#pragma unroll
    for (int o = 16; o; o >>= 1) {
        s0 += __shfl_xor_sync(FULL, s0, o);
        s1 += __shfl_xor_sync(FULL, s1, o);
        s2 += __shfl_xor_sync(FULL, s2, o);
        s3 += __shfl_xor_sync(FULL, s3, o);
    }
    float inv0 = 1.f / (s0 + 1e-16f), inv1 = 1.f / (s1 + 1e-16f);
    float inv2 = 1.f / (s2 + 1e-16f), inv3 = 1.f / (s3 + 1e-16f);

    float a0 = 0.f, a1 = 0.f, a2 = 0.f, a3 = 0.f;
    int i = s;
    while (i < e) {
        int cnt = min(32, e - i);
        float w0 = 0.f, w1 = 0.f, w2 = 0.f, w3 = 0.f;
        int msrc = 0;
        if (lane < cnt) {
            msrc = csr[i + lane];
            float4 as = *(const float4*)(alpha_s + (size_t)msrc * 4);
            w0 = __expf(lrelu(as.x + ad.x) - m0) * inv0;
            w1 = __expf(lrelu(as.y + ad.y) - m1) * inv1;
            w2 = __expf(lrelu(as.z + ad.z) - m2) * inv2;
            w3 = __expf(lrelu(as.w + ad.w) - m3) * inv3;
        }
        for (int j = 0; j < cnt; j++) {
            int src = __shfl_sync(FULL, msrc, j);
            float b0 = __shfl_sync(FULL, w0, j);
            float b1 = __shfl_sync(FULL, w1, j);
            float b2 = __shfl_sync(FULL, w2, j);
            float b3 = __shfl_sync(FULL, w3, j);
            const float* hp = hs + (size_t)src * DD;
            a0 += hp[lane]      * b0;
            a1 += hp[lane + 32] * b1;
            a2 += hp[lane + 64] * b2;
            a3 += hp[lane + 96] * b3;
        }
        i += cnt;
    }
    float* op = out + (size_t)wid * DD;
    op[lane]      = eluf(a0 + bias[lane]);
    op[lane + 32] = eluf(a1 + bias[lane + 32]);
    op[lane + 64] = eluf(a2 + bias[lane + 64]);
    op[lane + 96] = eluf(a3 + bias[lane + 96]);
}

// ---------------- host orchestration ----------------
extern "C" void kernel_launch(void* const* d_in, const int* in_sizes, int n_in,
                              void* d_out, int out_size) {
    (void)in_sizes; (void)n_in; (void)out_size;
    const float* x_food     = (const float*)d_in[0];
    const float* x_nut      = (const float*)d_in[1];
    const float* Wsrc_fn    = (const float*)d_in[2];
    const float* Wdst_fn    = (const float*)d_in[3];
    const float* att_src_fn = (const float*)d_in[4];
    const float* att_dst_fn = (const float*)d_in[5];
    const float* bias_fn    = (const float*)d_in[6];
    const float* Wsrc_nf    = (const float*)d_in[7];
    const float* Wdst_nf    = (const float*)d_in[8];
    const float* att_src_nf = (const float*)d_in[9];
    const float* att_dst_nf = (const float*)d_in[10];
    const float* bias_nf    = (const float*)d_in[11];
    const int*   ei_fn      = (const int*)d_in[12];
    const int*   ei_nf      = (const int*)d_in[13];
    float* out = (float*)d_out;

    float *hs0, *hs1, *hf, *hn, *as0, *as1, *ad0, *ad1, *Ad0, *Ad1;
    int *off0, *off1, *cur0, *cur1, *csr0, *csr1;
    cudaGetSymbolAddress((void**)&hs0,  g_hs0);
    cudaGetSymbolAddress((void**)&hs1,  g_hs1);
    cudaGetSymbolAddress((void**)&hf,   g_hfood);
    cudaGetSymbolAddress((void**)&hn,   g_hnut);
    cudaGetSymbolAddress((void**)&as0,  g_as0);
    cudaGetSymbolAddress((void**)&as1,  g_as1);
    cudaGetSymbolAddress((void**)&ad0,  g_ad0);
    cudaGetSymbolAddress((void**)&ad1,  g_ad1);
    cudaGetSymbolAddress((void**)&Ad0,  g_Ad0);
    cudaGetSymbolAddress((void**)&Ad1,  g_Ad1);
    cudaGetSymbolAddress((void**)&off0, g_off0);
    cudaGetSymbolAddress((void**)&off1, g_off1);
    cudaGetSymbolAddress((void**)&cur0, g_cur0);
    cudaGetSymbolAddress((void**)&cur1, g_cur1);
    cudaGetSymbolAddress((void**)&csr0, g_csr0);
    cudaGetSymbolAddress((void**)&csr1, g_csr1);

    // CSR build (edge lists shared across layers)
    zero2<<<196, 256>>>(off0, off1, NN + 1);
    hist2<<<512, 256>>>(ei_fn + EE, ei_nf + EE, off0, off1, EE);
    scan2<<<2, 1024>>>(off0, off1, NN + 1);
    copy2<<<196, 256>>>(off0, off1, cur0, cur1, NN);
    fill2<<<512, 256>>>(ei_fn, ei_nf, cur0, cur1, csr0, csr1, EE);

    int gblocks = (NN + 127) / 128;
    int ablocks = (NN * 32 + 255) / 256;
    int aggblocks = (2 * NN * 32 + 255) / 256;

    for (int l = 0; l < 2; l++) {
        const float* hfeat = l ? hf : x_food;
        const float* nfeat = l ? hn : x_nut;
        // rel0 = fn (src food -> dst nut), rel1 = nf (src nut -> dst food)
        gemm_tc<<<dim3(gblocks, 2), 256>>>(
            hfeat, nfeat, Wsrc_fn + l * DD * DD, Wsrc_nf + l * DD * DD,
            att_src_fn + l * DD, att_src_nf + l * DD, hs0, hs1, as0, as1);
        avec2<<<2, 128>>>(Wdst_fn + l * DD * DD, Wdst_nf + l * DD * DD,
                          att_dst_fn + l * DD, att_dst_nf + l * DD, Ad0, Ad1);
        alpha2<<<dim3(ablocks, 2), 256>>>(nfeat, hfeat, Ad0, Ad1, ad0, ad1);
        float* o_nut  = l ? (out + (size_t)NN * DD) : hn;
        float* o_food = l ? out : hf;
        gat_aggregate2<<<aggblocks, 256>>>(
            hs0, as0, ad0, off0, csr0, bias_fn + l * DD, o_nut,
            hs1, as1, ad1, off1, csr1, bias_nf + l * DD, o_food);
    }
}

// round 5
// speedup vs baseline: 1.2930x; 1.2930x over previous
#include <cuda_runtime.h>
#include <cuda_fp16.h>
#include <math.h>
#include <stdint.h>

#define NN 50000
#define DD 128
#define EE 800000
#define FULL 0xffffffffu

// ---------------- scratch (device globals; no allocation) ----------------
__device__ __align__(16) __half g_hs0[NN * DD];
__device__ __align__(16) __half g_hs1[NN * DD];
__device__ __align__(16) float g_hfood[NN * DD];
__device__ __align__(16) float g_hnut[NN * DD];
__device__ __align__(16) float g_as0[NN * 4];
__device__ __align__(16) float g_as1[NN * 4];
__device__ __align__(16) float g_ad0[NN * 4];
__device__ __align__(16) float g_ad1[NN * 4];
__device__ __align__(16) float g_Ad0[DD * 4];
__device__ __align__(16) float g_Ad1[DD * 4];
__device__ int g_off0[NN + 1];
__device__ int g_off1[NN + 1];
__device__ int g_cur0[NN];
__device__ int g_cur1[NN];
__device__ int g_csr0[EE];
__device__ int g_csr1[EE];

__device__ __forceinline__ float lrelu(float x) { return x > 0.f ? x : 0.2f * x; }
__device__ __forceinline__ float eluf(float x) { return x > 0.f ? x : expm1f(x); }

// ---------------- fused GEMM + alpha_s + alpha_d epilogue ----------------
// Y[N,128](fp16) = X[N,128] @ W[128,128]
// AS[n,h] = sum_c Y[n, h*32+c] * att[h*32+c]          (alpha_src of this rel)
// AD[n,h] = sum_d X[n,d] * Ad[d,h]                    (alpha_dst of OTHER rel;
//            this rel's X is the other rel's dst features)
// block: 256 threads = 16x16, each thread 8x8. Tile 128 rows x 128 cols.
// grid: (391, 2) -- blockIdx.y selects relation.
__global__ __launch_bounds__(256) void gemm_fused(
    const float* __restrict__ X0, const float* __restrict__ X1,
    const float* __restrict__ W0, const float* __restrict__ W1,
    const float* __restrict__ att0, const float* __restrict__ att1,
    __half* __restrict__ Y0, __half* __restrict__ Y1,
    float* __restrict__ AS0, float* __restrict__ AS1,
    const float* __restrict__ AdA, const float* __restrict__ AdB,
    float* __restrict__ ADout0, float* __restrict__ ADout1) {
    int rel = blockIdx.y;
    const float* __restrict__ X   = rel ? X1 : X0;
    const float* __restrict__ W   = rel ? W1 : W0;
    const float* __restrict__ att = rel ? att1 : att0;
    __half* __restrict__ Y  = rel ? Y1 : Y0;
    float* __restrict__ AS  = rel ? AS1 : AS0;
    // rel0: X=food = dst of rel1 -> produce ad1 using Ad1(=AdB)
    // rel1: X=nut  = dst of rel0 -> produce ad0 using Ad0(=AdA)
    const float* __restrict__ Adv = rel ? AdA : AdB;
    float* __restrict__ ADout     = rel ? ADout0 : ADout1;

    __shared__ float Xs[16][128];
    __shared__ float Ws[16][128];
    __shared__ float Ads[128][4];

    int tid = threadIdx.x;
    int tx = tid & 15, ty = tid >> 4;
    int rowBase = blockIdx.x * 128;
    int r0 = ty * 8, c0 = tx * 8;

    if (tid < 128) *(float4*)&Ads[tid][0] = ((const float4*)Adv)[tid];

    float acc[8][8];
#pragma unroll
    for (int i = 0; i < 8; i++)
#pragma unroll
        for (int j = 0; j < 8; j++) acc[i][j] = 0.f;

    float adacc[4] = {0.f, 0.f, 0.f, 0.f};

    int xrow = tid & 127;
    int xk4  = (tid >> 7) * 8;       // 0 or 8
    int grow = rowBase + xrow;
    bool xvalid = grow < NN;
    const float* Xbase = X + (size_t)grow * DD;
    int wk = tid >> 4;               // 0..15
    int wc = (tid & 15) * 8;

#pragma unroll
    for (int k0 = 0; k0 < 128; k0 += 16) {
        float4 a0 = xvalid ? *(const float4*)(Xbase + k0 + xk4)
                           : make_float4(0.f, 0.f, 0.f, 0.f);
        float4 a1 = xvalid ? *(const float4*)(Xbase + k0 + xk4 + 4)
                           : make_float4(0.f, 0.f, 0.f, 0.f);
        float4 b0 = *(const float4*)(W + (size_t)(k0 + wk) * DD + wc);
        float4 b1 = *(const float4*)(W + (size_t)(k0 + wk) * DD + wc + 4);
        __syncthreads();
        Xs[xk4 + 0][xrow] = a0.x; Xs[xk4 + 1][xrow] = a0.y;
        Xs[xk4 + 2][xrow] = a0.z; Xs[xk4 + 3][xrow] = a0.w;
        Xs[xk4 + 4][xrow] = a1.x; Xs[xk4 + 5][xrow] = a1.y;
        Xs[xk4 + 6][xrow] = a1.z; Xs[xk4 + 7][xrow] = a1.w;
        *(float4*)&Ws[wk][wc]     = b0;
        *(float4*)&Ws[wk][wc + 4] = b1;
        __syncthreads();
#pragma unroll
        for (int kk = 0; kk < 16; kk++) {
            float xr[8], wr[8];
            *(float4*)(xr)     = *(const float4*)&Xs[kk][r0];
            *(float4*)(xr + 4) = *(const float4*)&Xs[kk][r0 + 4];
            *(float4*)(wr)     = *(const float4*)&Ws[kk][c0];
            *(float4*)(wr + 4) = *(const float4*)&Ws[kk][c0 + 4];
#pragma unroll
            for (int i = 0; i < 8; i++)
#pragma unroll
                for (int j = 0; j < 8; j++) acc[i][j] += xr[i] * wr[j];
        }
        // fused alpha_d: threads 0..127, row = tid
        if (tid < 128) {
#pragma unroll
            for (int kk = 0; kk < 16; kk++) {
                float xv = Xs[kk][tid];
                adacc[0] += xv * Ads[k0 + kk][0];
                adacc[1] += xv * Ads[k0 + kk][1];
                adacc[2] += xv * Ads[k0 + kk][2];
                adacc[3] += xv * Ads[k0 + kk][3];
            }
        }
    }

    if (tid < 128 && rowBase + tid < NN)
        *(float4*)(ADout + (size_t)(rowBase + tid) * 4) =
            make_float4(adacc[0], adacc[1], adacc[2], adacc[3]);

    // epilogue: store Y (fp16) and fused alpha_s
    float av[8];
#pragma unroll
    for (int j = 0; j < 8; j++) av[j] = att[c0 + j];
    int h = tx >> 2;
#pragma unroll
    for (int i = 0; i < 8; i++) {
        int gr = rowBase + r0 + i;
        if (gr < NN) {
            __half2 hh[4];
            hh[0] = __floats2half2_rn(acc[i][0], acc[i][1]);
            hh[1] = __floats2half2_rn(acc[i][2], acc[i][3]);
            hh[2] = __floats2half2_rn(acc[i][4], acc[i][5]);
            hh[3] = __floats2half2_rn(acc[i][6], acc[i][7]);
            *(uint4*)(Y + (size_t)gr * DD + c0) = *(uint4*)hh;
        }
        float p = acc[i][0] * av[0] + acc[i][1] * av[1] + acc[i][2] * av[2] +
                  acc[i][3] * av[3] + acc[i][4] * av[4] + acc[i][5] * av[5] +
                  acc[i][6] * av[6] + acc[i][7] * av[7];
        p += __shfl_xor_sync(FULL, p, 1);
        p += __shfl_xor_sync(FULL, p, 2);
        if ((tx & 3) == 0 && gr < NN) AS[(size_t)gr * 4 + h] = p;
    }
}

// ---------------- Avec: Ad[d,h] = sum_c Wdst[d, h*32+c] * att[h,c] ----------------
__global__ void avec2(const float* __restrict__ Wd0, const float* __restrict__ Wd1,
                      const float* __restrict__ at0, const float* __restrict__ at1,
                      float* __restrict__ Ad0, float* __restrict__ Ad1) {
    int rel = blockIdx.x;
    const float* W = rel ? Wd1 : Wd0;
    const float* att = rel ? at1 : at0;
    float* out = rel ? Ad1 : Ad0;
    int d = threadIdx.x;
#pragma unroll
    for (int hh = 0; hh < 4; hh++) {
        float s = 0.f;
#pragma unroll
        for (int c = 0; c < 32; c++) s += W[d * 128 + hh * 32 + c] * att[hh * 32 + c];
        out[d * 4 + hh] = s;
    }
}

// ---------------- CSR build (fused over both relations) ----------------
__global__ void zero2(int* __restrict__ a, int* __restrict__ b, int n) {
    for (int i = blockIdx.x * blockDim.x + threadIdx.x; i < n; i += gridDim.x * blockDim.x) {
        a[i] = 0; b[i] = 0;
    }
}
__global__ void hist2(const int* __restrict__ d0, const int* __restrict__ d1,
                      int* __restrict__ c0, int* __restrict__ c1, int n) {
    for (int i = blockIdx.x * blockDim.x + threadIdx.x; i < n; i += gridDim.x * blockDim.x) {
        atomicAdd(&c0[d0[i] + 1], 1);
        atomicAdd(&c1[d1[i] + 1], 1);
    }
}
__global__ __launch_bounds__(1024) void scan2(int* __restrict__ a0, int* __restrict__ a1, int n) {
    int* a = blockIdx.x ? a1 : a0;
    __shared__ int warpsum[32];
    __shared__ int carry_s;
    int tid = threadIdx.x, lane = tid & 31, w = tid >> 5;
    if (tid == 0) carry_s = 0;
    __syncthreads();
    for (int base = 0; base < n; base += 1024) {
        int idx = base + tid;
        int v = (idx < n) ? a[idx] : 0;
        int x = v;
#pragma unroll
        for (int o = 1; o < 32; o <<= 1) {
            int t = __shfl_up_sync(FULL, x, o);
            if (lane >= o) x += t;
        }
        if (lane == 31) warpsum[w] = x;
        __syncthreads();
        if (w == 0) {
            int y = warpsum[lane];
#pragma unroll
            for (int o = 1; o < 32; o <<= 1) {
                int t = __shfl_up_sync(FULL, y, o);
                if (lane >= o) y += t;
            }
            warpsum[lane] = y;
        }
        __syncthreads();
        int incl = x + (w > 0 ? warpsum[w - 1] : 0);
        int carry = carry_s;
        if (idx < n) a[idx] = carry + incl;
        __syncthreads();
        if (tid == 1023) carry_s = carry + warpsum[31];
        __syncthreads();
    }
}
__global__ void copy2(const int* __restrict__ o0, const int* __restrict__ o1,
                      int* __restrict__ c0, int* __restrict__ c1, int n) {
    for (int i = blockIdx.x * blockDim.x + threadIdx.x; i < n; i += gridDim.x * blockDim.x) {
        c0[i] = o0[i]; c1[i] = o1[i];
    }
}
__global__ void fill2(const int* __restrict__ e0, const int* __restrict__ e1,
                      int* __restrict__ cu0, int* __restrict__ cu1,
                      int* __restrict__ cs0, int* __restrict__ cs1, int n) {
    for (int i = blockIdx.x * blockDim.x + threadIdx.x; i < n; i += gridDim.x * blockDim.x) {
        int p0 = atomicAdd(&cu0[e0[n + i]], 1);
        cs0[p0] = e0[i];
        int p1 = atomicAdd(&cu1[e1[n + i]], 1);
        cs1[p1] = e1[i];
    }
}

// ---------------- GAT aggregation (both relations) + ELU epilogue ----------------
// hs is fp16 (half2 gathers). Lane covers channels {2*lane, 2*lane+1} and
// {64+2*lane, 64+2*lane+1}; head = lane/16 (+2 for the upper block).
__global__ __launch_bounds__(256) void gat_aggregate2(
    const __half2* __restrict__ hsA, const float* __restrict__ asA,
    const float* __restrict__ adA, const int* __restrict__ offA,
    const int* __restrict__ csrA, const float* __restrict__ bA, float* __restrict__ oA,
    const __half2* __restrict__ hsB, const float* __restrict__ asB,
    const float* __restrict__ adB, const int* __restrict__ offB,
    const int* __restrict__ csrB, const float* __restrict__ bB, float* __restrict__ oB) {
    int gwid = (blockIdx.x * blockDim.x + threadIdx.x) >> 5;
    if (gwid >= 2 * NN) return;
    int rel = gwid >= NN;
    int wid = gwid - rel * NN;
    int lane = threadIdx.x & 31;
    const __half2* __restrict__ hs    = rel ? hsB : hsA;
    const float* __restrict__ alpha_s = rel ? asB : asA;
    const float* __restrict__ alpha_d = rel ? adB : adA;
    const int* __restrict__ off       = rel ? offB : offA;
    const int* __restrict__ csr       = rel ? csrB : csrA;
    const float* __restrict__ bias    = rel ? bB : bA;
    float* __restrict__ out           = rel ? oB : oA;

    int s = off[wid], e = off[wid + 1];
    float4 ad = *(const float4*)(alpha_d + (size_t)wid * 4);

    float m0 = -3e38f, m1 = -3e38f, m2 = -3e38f, m3 = -3e38f;
    for (int i = s + lane; i < e; i += 32) {
        int src = csr[i];
        float4 as = *(const float4*)(alpha_s + (size_t)src * 4);
        m0 = fmaxf(m0, lrelu(as.x + ad.x));
        m1 = fmaxf(m1, lrelu(as.y + ad.y));
        m2 = fmaxf(m2, lrelu(as.z + ad.z));
        m3 = fmaxf(m3, lrelu(as.w + ad.w));
    }
#pragma unroll
    for (int o = 16; o; o >>= 1) {
        m0 = fmaxf(m0, __shfl_xor_sync(FULL, m0, o));
        m1 = fmaxf(m1, __shfl_xor_sync(FULL, m1, o));
        m2 = fmaxf(m2, __shfl_xor_sync(FULL, m2, o));
        m3 = fmaxf(m3, __shfl_xor_sync(FULL, m3, o));
    }
    float s0 = 0.f, s1 = 0.f, s2 = 0.f, s3 = 0.f;
    for (int i = s + lane; i < e; i += 32) {
        int src = csr[i];
        float4 as = *(const float4*)(alpha_s + (size_t)src * 4);
        s0 += __expf(lrelu(as.x + ad.x) - m0);
        s1 += __expf(lrelu(as.y + ad.y) - m1);
        s2 += __expf(lrelu(as.z + ad.z) - m2);
        s3 += __expf(lrelu(as.w + ad.w) - m3);
    }
#pragma unroll
    for (int o = 16; o; o >>= 1) {
        s0 += __shfl_xor_sync(FULL, s0, o);
        s1 += __shfl_xor_sync(FULL, s1, o);
        s2 += __shfl_xor_sync(FULL, s2, o);
        s3 += __shfl_xor_sync(FULL, s3, o);
    }
    float inv0 = 1.f / (s0 + 1e-16f), inv1 = 1.f / (s1 + 1e-16f);
    float inv2 = 1.f / (s2 + 1e-16f), inv3 = 1.f / (s3 + 1e-16f);

    float2 accA = make_float2(0.f, 0.f);
    float2 accB = make_float2(0.f, 0.f);
    bool hi = lane >= 16;
    int i = s;
    while (i < e) {
        int cnt = min(32, e - i);
        float w0 = 0.f, w1 = 0.f, w2 = 0.f, w3 = 0.f;
        int msrc = 0;
        if (lane < cnt) {
            msrc = csr[i + lane];
            float4 as = *(const float4*)(alpha_s + (size_t)msrc * 4);
            w0 = __expf(lrelu(as.x + ad.x) - m0) * inv0;
            w1 = __expf(lrelu(as.y + ad.y) - m1) * inv1;
            w2 = __expf(lrelu(as.z + ad.z) - m2) * inv2;
            w3 = __expf(lrelu(as.w + ad.w) - m3) * inv3;
        }
        for (int j = 0; j < cnt; j++) {
            int src = __shfl_sync(FULL, msrc, j);
            float b0 = __shfl_sync(FULL, w0, j);
            float b1 = __shfl_sync(FULL, w1, j);
            float b2 = __shfl_sync(FULL, w2, j);
            float b3 = __shfl_sync(FULL, w3, j);
            const __half2* hp = hs + (size_t)src * 64;
            float2 v0 = __half22float2(hp[lane]);
            float2 v1 = __half22float2(hp[lane + 32]);
            float bA = hi ? b1 : b0;
            float bB = hi ? b3 : b2;
            accA.x += v0.x * bA; accA.y += v0.y * bA;
            accB.x += v1.x * bB; accB.y += v1.y * bB;
        }
        i += cnt;
    }
    float* op = out + (size_t)wid * DD;
    float2 bv0 = *(const float2*)(bias + 2 * lane);
    float2 bv1 = *(const float2*)(bias + 64 + 2 * lane);
    *(float2*)(op + 2 * lane) =
        make_float2(eluf(accA.x + bv0.x), eluf(accA.y + bv0.y));
    *(float2*)(op + 64 + 2 * lane) =
        make_float2(eluf(accB.x + bv1.x), eluf(accB.y + bv1.y));
}

// ---------------- host orchestration ----------------
extern "C" void kernel_launch(void* const* d_in, const int* in_sizes, int n_in,
                              void* d_out, int out_size) {
    (void)in_sizes; (void)n_in; (void)out_size;
    const float* x_food     = (const float*)d_in[0];
    const float* x_nut      = (const float*)d_in[1];
    const float* Wsrc_fn    = (const float*)d_in[2];
    const float* Wdst_fn    = (const float*)d_in[3];
    const float* att_src_fn = (const float*)d_in[4];
    const float* att_dst_fn = (const float*)d_in[5];
    const float* bias_fn    = (const float*)d_in[6];
    const float* Wsrc_nf    = (const float*)d_in[7];
    const float* Wdst_nf    = (const float*)d_in[8];
    const float* att_src_nf = (const float*)d_in[9];
    const float* att_dst_nf = (const float*)d_in[10];
    const float* bias_nf    = (const float*)d_in[11];
    const int*   ei_fn      = (const int*)d_in[12];
    const int*   ei_nf      = (const int*)d_in[13];
    float* out = (float*)d_out;

    __half *hs0, *hs1;
    float *hf, *hn, *as0, *as1, *ad0, *ad1, *Ad0, *Ad1;
    int *off0, *off1, *cur0, *cur1, *csr0, *csr1;
    cudaGetSymbolAddress((void**)&hs0,  g_hs0);
    cudaGetSymbolAddress((void**)&hs1,  g_hs1);
    cudaGetSymbolAddress((void**)&hf,   g_hfood);
    cudaGetSymbolAddress((void**)&hn,   g_hnut);
    cudaGetSymbolAddress((void**)&as0,  g_as0);
    cudaGetSymbolAddress((void**)&as1,  g_as1);
    cudaGetSymbolAddress((void**)&ad0,  g_ad0);
    cudaGetSymbolAddress((void**)&ad1,  g_ad1);
    cudaGetSymbolAddress((void**)&Ad0,  g_Ad0);
    cudaGetSymbolAddress((void**)&Ad1,  g_Ad1);
    cudaGetSymbolAddress((void**)&off0, g_off0);
    cudaGetSymbolAddress((void**)&off1, g_off1);
    cudaGetSymbolAddress((void**)&cur0, g_cur0);
    cudaGetSymbolAddress((void**)&cur1, g_cur1);
    cudaGetSymbolAddress((void**)&csr0, g_csr0);
    cudaGetSymbolAddress((void**)&csr1, g_csr1);

    int gblocks = (NN + 127) / 128;
    int aggblocks = (2 * NN * 32 + 255) / 256;

    // launch order chosen so index-3 launch (the one ncu captures) is gemm_fused
    avec2<<<2, 128>>>(Wdst_fn, Wdst_nf, att_dst_fn, att_dst_nf, Ad0, Ad1);   // 0
    zero2<<<196, 256>>>(off0, off1, NN + 1);                                  // 1
    hist2<<<512, 256>>>(ei_fn + EE, ei_nf + EE, off0, off1, EE);              // 2
    gemm_fused<<<dim3(gblocks, 2), 256>>>(                                    // 3 (profiled)
        x_food, x_nut, Wsrc_fn, Wsrc_nf, att_src_fn, att_src_nf,
        hs0, hs1, as0, as1, Ad0, Ad1, ad0, ad1);
    scan2<<<2, 1024>>>(off0, off1, NN + 1);                                   // 4
    copy2<<<196, 256>>>(off0, off1, cur0, cur1, NN);                          // 5
    fill2<<<512, 256>>>(ei_fn, ei_nf, cur0, cur1, csr0, csr1, EE);            // 6
    gat_aggregate2<<<aggblocks, 256>>>(                                       // 7
        (const __half2*)hs0, as0, ad0, off0, csr0, bias_fn, hn,
        (const __half2*)hs1, as1, ad1, off1, csr1, bias_nf, hf);

    // layer 2
    avec2<<<2, 128>>>(Wdst_fn + DD * DD, Wdst_nf + DD * DD,
                      att_dst_fn + DD, att_dst_nf + DD, Ad0, Ad1);            // 8
    gemm_fused<<<dim3(gblocks, 2), 256>>>(                                    // 9
        hf, hn, Wsrc_fn + DD * DD, Wsrc_nf + DD * DD,
        att_src_fn + DD, att_src_nf + DD,
        hs0, hs1, as0, as1, Ad0, Ad1, ad0, ad1);
    gat_aggregate2<<<aggblocks, 256>>>(                                       // 10
        (const __half2*)hs0, as0, ad0, off0, csr0, bias_fn + DD,
        out + (size_t)NN * DD,
        (const __half2*)hs1, as1, ad1, off1, csr1, bias_nf + DD, out);
}

// round 6
// speedup vs baseline: 1.5718x; 1.2156x over previous
#include <cuda_runtime.h>
#include <cuda_fp16.h>
#include <math.h>
#include <stdint.h>

#define NN 50000
#define DD 128
#define EE 800000
#define FULL 0xffffffffu

// ---------------- scratch (device globals; no allocation) ----------------
__device__ __align__(16) __half g_hs0[NN * DD];
__device__ __align__(16) __half g_hs1[NN * DD];
__device__ __align__(16) float g_hfood[NN * DD];
__device__ __align__(16) float g_hnut[NN * DD];
__device__ __align__(16) float g_as0[NN * 4];
__device__ __align__(16) float g_as1[NN * 4];
__device__ __align__(16) float g_ad0[NN * 4];
__device__ __align__(16) float g_ad1[NN * 4];
__device__ __align__(16) float g_Ad0[DD * 4];
__device__ __align__(16) float g_Ad1[DD * 4];
__device__ int g_off0[NN + 1];
__device__ int g_off1[NN + 1];
__device__ int g_cur0[NN];
__device__ int g_cur1[NN];
__device__ int g_csr0[EE];
__device__ int g_csr1[EE];

__device__ __forceinline__ float lrelu(float x) { return x > 0.f ? x : 0.2f * x; }
__device__ __forceinline__ float eluf(float x) { return x > 0.f ? x : expm1f(x); }

// ---------------- fused GEMM + alpha_s epilogue (fp16 Y) ----------------
// Y[N,128](fp16) = X[N,128] @ W[128,128]
// AS[n,h] = sum_c Yf32[n, h*32+c] * att[h*32+c]
// block: 256 threads = 16x16, each thread 8x8. Tile 128 rows x 128 cols.
// grid: (391, 2) -- blockIdx.y selects relation.
__global__ __launch_bounds__(256, 2) void gemm_fused(
    const float* __restrict__ X0, const float* __restrict__ X1,
    const float* __restrict__ W0, const float* __restrict__ W1,
    const float* __restrict__ att0, const float* __restrict__ att1,
    __half* __restrict__ Y0, __half* __restrict__ Y1,
    float* __restrict__ AS0, float* __restrict__ AS1) {
    int rel = blockIdx.y;
    const float* __restrict__ X   = rel ? X1 : X0;
    const float* __restrict__ W   = rel ? W1 : W0;
    const float* __restrict__ att = rel ? att1 : att0;
    __half* __restrict__ Y  = rel ? Y1 : Y0;
    float* __restrict__ AS  = rel ? AS1 : AS0;

    __shared__ float Xs[16][128];
    __shared__ float Ws[16][128];

    int tid = threadIdx.x;
    int tx = tid & 15, ty = tid >> 4;
    int rowBase = blockIdx.x * 128;
    int r0 = ty * 8, c0 = tx * 8;

    float acc[8][8];
#pragma unroll
    for (int i = 0; i < 8; i++)
#pragma unroll
        for (int j = 0; j < 8; j++) acc[i][j] = 0.f;

    int xrow = tid & 127;
    int xk4  = (tid >> 7) * 8;       // 0 or 8
    int grow = rowBase + xrow;
    bool xvalid = grow < NN;
    const float* Xbase = X + (size_t)grow * DD;
    int wk = tid >> 4;               // 0..15
    int wc = (tid & 15) * 8;

#pragma unroll
    for (int k0 = 0; k0 < 128; k0 += 16) {
        float4 a0 = xvalid ? *(const float4*)(Xbase + k0 + xk4)
                           : make_float4(0.f, 0.f, 0.f, 0.f);
        float4 a1 = xvalid ? *(const float4*)(Xbase + k0 + xk4 + 4)
                           : make_float4(0.f, 0.f, 0.f, 0.f);
        float4 b0 = *(const float4*)(W + (size_t)(k0 + wk) * DD + wc);
        float4 b1 = *(const float4*)(W + (size_t)(k0 + wk) * DD + wc + 4);
        __syncthreads();
        Xs[xk4 + 0][xrow] = a0.x; Xs[xk4 + 1][xrow] = a0.y;
        Xs[xk4 + 2][xrow] = a0.z; Xs[xk4 + 3][xrow] = a0.w;
        Xs[xk4 + 4][xrow] = a1.x; Xs[xk4 + 5][xrow] = a1.y;
        Xs[xk4 + 6][xrow] = a1.z; Xs[xk4 + 7][xrow] = a1.w;
        *(float4*)&Ws[wk][wc]     = b0;
        *(float4*)&Ws[wk][wc + 4] = b1;
        __syncthreads();
#pragma unroll
        for (int kk = 0; kk < 16; kk++) {
            float xr[8], wr[8];
            *(float4*)(xr)     = *(const float4*)&Xs[kk][r0];
            *(float4*)(xr + 4) = *(const float4*)&Xs[kk][r0 + 4];
            *(float4*)(wr)     = *(const float4*)&Ws[kk][c0];
            *(float4*)(wr + 4) = *(const float4*)&Ws[kk][c0 + 4];
#pragma unroll
            for (int i = 0; i < 8; i++)
#pragma unroll
                for (int j = 0; j < 8; j++) acc[i][j] += xr[i] * wr[j];
        }
    }

    // epilogue: store Y (fp16) and fused alpha_s
    float av[8];
#pragma unroll
    for (int j = 0; j < 8; j++) av[j] = att[c0 + j];
    int h = tx >> 2;
#pragma unroll
    for (int i = 0; i < 8; i++) {
        int gr = rowBase + r0 + i;
        if (gr < NN) {
            __half2 hh[4];
            hh[0] = __floats2half2_rn(acc[i][0], acc[i][1]);
            hh[1] = __floats2half2_rn(acc[i][2], acc[i][3]);
            hh[2] = __floats2half2_rn(acc[i][4], acc[i][5]);
            hh[3] = __floats2half2_rn(acc[i][6], acc[i][7]);
            *(uint4*)(Y + (size_t)gr * DD + c0) = *(uint4*)hh;
        }
        float p = acc[i][0] * av[0] + acc[i][1] * av[1] + acc[i][2] * av[2] +
                  acc[i][3] * av[3] + acc[i][4] * av[4] + acc[i][5] * av[5] +
                  acc[i][6] * av[6] + acc[i][7] * av[7];
        p += __shfl_xor_sync(FULL, p, 1);
        p += __shfl_xor_sync(FULL, p, 2);
        if ((tx & 3) == 0 && gr < NN) AS[(size_t)gr * 4 + h] = p;
    }
}

// ---------------- Avec: Ad[d,h] = sum_c Wdst[d, h*32+c] * att[h,c] ----------------
__global__ void avec2(const float* __restrict__ Wd0, const float* __restrict__ Wd1,
                      const float* __restrict__ at0, const float* __restrict__ at1,
                      float* __restrict__ Ad0, float* __restrict__ Ad1) {
    int rel = blockIdx.x;
    const float* W = rel ? Wd1 : Wd0;
    const float* att = rel ? at1 : at0;
    float* out = rel ? Ad1 : Ad0;
    int d = threadIdx.x;
#pragma unroll
    for (int hh = 0; hh < 4; hh++) {
        float s = 0.f;
#pragma unroll
        for (int c = 0; c < 32; c++) s += W[d * 128 + hh * 32 + c] * att[hh * 32 + c];
        out[d * 4 + hh] = s;
    }
}

// ---------------- alpha_d[n,h] = xd[n,:] @ Ad[:,h] (warp per node) ----------------
__global__ __launch_bounds__(256) void alpha2(const float* __restrict__ xd0,
                                              const float* __restrict__ xd1,
                                              const float* __restrict__ Ad0,
                                              const float* __restrict__ Ad1,
                                              float* __restrict__ out0,
                                              float* __restrict__ out1) {
    int rel = blockIdx.y;
    const float* x = rel ? xd1 : xd0;
    const float* avec = rel ? Ad1 : Ad0;
    float* alpha = rel ? out1 : out0;
    int wid = (blockIdx.x * blockDim.x + threadIdx.x) >> 5;
    int lane = threadIdx.x & 31;
    if (wid >= NN) return;
    float p0 = 0.f, p1 = 0.f, p2 = 0.f, p3 = 0.f;
#pragma unroll
    for (int j = 0; j < 4; j++) {
        int d = lane + j * 32;
        float xv = x[(size_t)wid * DD + d];
        float4 av = *(const float4*)(avec + d * 4);
        p0 += xv * av.x; p1 += xv * av.y; p2 += xv * av.z; p3 += xv * av.w;
    }
#pragma unroll
    for (int o = 16; o; o >>= 1) {
        p0 += __shfl_xor_sync(FULL, p0, o);
        p1 += __shfl_xor_sync(FULL, p1, o);
        p2 += __shfl_xor_sync(FULL, p2, o);
        p3 += __shfl_xor_sync(FULL, p3, o);
    }
    if (lane == 0) *(float4*)(alpha + (size_t)wid * 4) = make_float4(p0, p1, p2, p3);
}

// ---------------- CSR build (fused over both relations) ----------------
__global__ void zero2(int* __restrict__ a, int* __restrict__ b, int n) {
    for (int i = blockIdx.x * blockDim.x + threadIdx.x; i < n; i += gridDim.x * blockDim.x) {
        a[i] = 0; b[i] = 0;
    }
}
__global__ void hist2(const int* __restrict__ d0, const int* __restrict__ d1,
                      int* __restrict__ c0, int* __restrict__ c1, int n) {
    for (int i = blockIdx.x * blockDim.x + threadIdx.x; i < n; i += gridDim.x * blockDim.x) {
        atomicAdd(&c0[d0[i] + 1], 1);
        atomicAdd(&c1[d1[i] + 1], 1);
    }
}
__global__ __launch_bounds__(1024) void scan2(int* __restrict__ a0, int* __restrict__ a1, int n) {
    int* a = blockIdx.x ? a1 : a0;
    __shared__ int warpsum[32];
    __shared__ int carry_s;
    int tid = threadIdx.x, lane = tid & 31, w = tid >> 5;
    if (tid == 0) carry_s = 0;
    __syncthreads();
    for (int base = 0; base < n; base += 1024) {
        int idx = base + tid;
        int v = (idx < n) ? a[idx] : 0;
        int x = v;
#pragma unroll
        for (int o = 1; o < 32; o <<= 1) {
            int t = __shfl_up_sync(FULL, x, o);
            if (lane >= o) x += t;
        }
        if (lane == 31) warpsum[w] = x;
        __syncthreads();
        if (w == 0) {
            int y = warpsum[lane];
#pragma unroll
            for (int o = 1; o < 32; o <<= 1) {
                int t = __shfl_up_sync(FULL, y, o);
                if (lane >= o) y += t;
            }
            warpsum[lane] = y;
        }
        __syncthreads();
        int incl = x + (w > 0 ? warpsum[w - 1] : 0);
        int carry = carry_s;
        if (idx < n) a[idx] = carry + incl;
        __syncthreads();
        if (tid == 1023) carry_s = carry + warpsum[31];
        __syncthreads();
    }
}
__global__ void copy2(const int* __restrict__ o0, const int* __restrict__ o1,
                      int* __restrict__ c0, int* __restrict__ c1, int n) {
    for (int i = blockIdx.x * blockDim.x + threadIdx.x; i < n; i += gridDim.x * blockDim.x) {
        c0[i] = o0[i]; c1[i] = o1[i];
    }
}
__global__ void fill2(const int* __restrict__ e0, const int* __restrict__ e1,
                      int* __restrict__ cu0, int* __restrict__ cu1,
                      int* __restrict__ cs0, int* __restrict__ cs1, int n) {
    for (int i = blockIdx.x * blockDim.x + threadIdx.x; i < n; i += gridDim.x * blockDim.x) {
        int p0 = atomicAdd(&cu0[e0[n + i]], 1);
        cs0[p0] = e0[i];
        int p1 = atomicAdd(&cu1[e1[n + i]], 1);
        cs1[p1] = e1[i];
    }
}

// ---------------- GAT aggregation (both relations) + ELU epilogue ----------------
// hs is fp16 (half2 gathers). Lane covers channels {2*lane, 2*lane+1} and
// {64+2*lane, 64+2*lane+1}.
__global__ __launch_bounds__(256) void gat_aggregate2(
    const __half2* __restrict__ hsA, const float* __restrict__ asA,
    const float* __restrict__ adA, const int* __restrict__ offA,
    const int* __restrict__ csrA, const float* __restrict__ bA, float* __restrict__ oA,
    const __half2* __restrict__ hsB, const float* __restrict__ asB,
    const float* __restrict__ adB, const int* __restrict__ offB,
    const int* __restrict__ csrB, const float* __restrict__ bB, float* __restrict__ oB) {
    int gwid = (blockIdx.x * blockDim.x + threadIdx.x) >> 5;
    if (gwid >= 2 * NN) return;
    int rel = gwid >= NN;
    int wid = gwid - rel * NN;
    int lane = threadIdx.x & 31;
    const __half2* __restrict__ hs    = rel ? hsB : hsA;
    const float* __restrict__ alpha_s = rel ? asB : asA;
    const float* __restrict__ alpha_d = rel ? adB : adA;
    const int* __restrict__ off       = rel ? offB : offA;
    const int* __restrict__ csr       = rel ? csrB : csrA;
    const float* __restrict__ bias    = rel ? bB : bA;
    float* __restrict__ out           = rel ? oB : oA;

    int s = off[wid], e = off[wid + 1];
    float4 ad = *(const float4*)(alpha_d + (size_t)wid * 4);

    float m0 = -3e38f, m1 = -3e38f, m2 = -3e38f, m3 = -3e38f;
    for (int i = s + lane; i < e; i += 32) {
        int src = csr[i];
        float4 as = *(const float4*)(alpha_s + (size_t)src * 4);
        m0 = fmaxf(m0, lrelu(as.x + ad.x));
        m1 = fmaxf(m1, lrelu(as.y + ad.y));
        m2 = fmaxf(m2, lrelu(as.z + ad.z));
        m3 = fmaxf(m3, lrelu(as.w + ad.w));
    }
#pragma unroll
    for (int o = 16; o; o >>= 1) {
        m0 = fmaxf(m0, __shfl_xor_sync(FULL, m0, o));
        m1 = fmaxf(m1, __shfl_xor_sync(FULL, m1, o));
        m2 = fmaxf(m2, __shfl_xor_sync(FULL, m2, o));
        m3 = fmaxf(m3, __shfl_xor_sync(FULL, m3, o));
    }
    float s0 = 0.f, s1 = 0.f, s2 = 0.f, s3 = 0.f;
    for (int i = s + lane; i < e; i += 32) {
        int src = csr[i];
        float4 as = *(const float4*)(alpha_s + (size_t)src * 4);
        s0 += __expf(lrelu(as.x + ad.x) - m0);
        s1 += __expf(lrelu(as.y + ad.y) - m1);
        s2 += __expf(lrelu(as.z + ad.z) - m2);
        s3 += __expf(lrelu(as.w + ad.w) - m3);
    }
#pragma unroll
    for (int o = 16; o; o >>= 1) {
        s0 += __shfl_xor_sync(FULL, s0, o);
        s1 += __shfl_xor_sync(FULL, s1, o);
        s2 += __shfl_xor_sync(FULL, s2, o);
        s3 += __shfl_xor_sync(FULL, s3, o);
    }
    float inv0 = 1.f / (s0 + 1e-16f), inv1 = 1.f / (s1 + 1e-16f);
    float inv2 = 1.f / (s2 + 1e-16f), inv3 = 1.f / (s3 + 1e-16f);

    float2 accA = make_float2(0.f, 0.f);
    float2 accB = make_float2(0.f, 0.f);
    bool hi = lane >= 16;
    int i = s;
    while (i < e) {
        int cnt = min(32, e - i);
        float w0 = 0.f, w1 = 0.f, w2 = 0.f, w3 = 0.f;
        int msrc = 0;
        if (lane < cnt) {
            msrc = csr[i + lane];
            float4 as = *(const float4*)(alpha_s + (size_t)msrc * 4);
            w0 = __expf(lrelu(as.x + ad.x) - m0) * inv0;
            w1 = __expf(lrelu(as.y + ad.y) - m1) * inv1;
            w2 = __expf(lrelu(as.z + ad.z) - m2) * inv2;
            w3 = __expf(lrelu(as.w + ad.w) - m3) * inv3;
        }
        for (int j = 0; j < cnt; j++) {
            int src = __shfl_sync(FULL, msrc, j);
            float b0 = __shfl_sync(FULL, w0, j);
            float b1 = __shfl_sync(FULL, w1, j);
            float b2 = __shfl_sync(FULL, w2, j);
            float b3 = __shfl_sync(FULL, w3, j);
            const __half2* hp = hs + (size_t)src * 64;
            float2 v0 = __half22float2(hp[lane]);
            float2 v1 = __half22float2(hp[lane + 32]);
            float bA = hi ? b1 : b0;
            float bB = hi ? b3 : b2;
            accA.x += v0.x * bA; accA.y += v0.y * bA;
            accB.x += v1.x * bB; accB.y += v1.y * bB;
        }
        i += cnt;
    }
    float* op = out + (size_t)wid * DD;
    float2 bv0 = *(const float2*)(bias + 2 * lane);
    float2 bv1 = *(const float2*)(bias + 64 + 2 * lane);
    *(float2*)(op + 2 * lane) =
        make_float2(eluf(accA.x + bv0.x), eluf(accA.y + bv0.y));
    *(float2*)(op + 64 + 2 * lane) =
        make_float2(eluf(accB.x + bv1.x), eluf(accB.y + bv1.y));
}

// ---------------- host orchestration ----------------
extern "C" void kernel_launch(void* const* d_in, const int* in_sizes, int n_in,
                              void* d_out, int out_size) {
    (void)in_sizes; (void)n_in; (void)out_size;
    const float* x_food     = (const float*)d_in[0];
    const float* x_nut      = (const float*)d_in[1];
    const float* Wsrc_fn    = (const float*)d_in[2];
    const float* Wdst_fn    = (const float*)d_in[3];
    const float* att_src_fn = (const float*)d_in[4];
    const float* att_dst_fn = (const float*)d_in[5];
    const float* bias_fn    = (const float*)d_in[6];
    const float* Wsrc_nf    = (const float*)d_in[7];
    const float* Wdst_nf    = (const float*)d_in[8];
    const float* att_src_nf = (const float*)d_in[9];
    const float* att_dst_nf = (const float*)d_in[10];
    const float* bias_nf    = (const float*)d_in[11];
    const int*   ei_fn      = (const int*)d_in[12];
    const int*   ei_nf      = (const int*)d_in[13];
    float* out = (float*)d_out;

    __half *hs0, *hs1;
    float *hf, *hn, *as0, *as1, *ad0, *ad1, *Ad0, *Ad1;
    int *off0, *off1, *cur0, *cur1, *csr0, *csr1;
    cudaGetSymbolAddress((void**)&hs0,  g_hs0);
    cudaGetSymbolAddress((void**)&hs1,  g_hs1);
    cudaGetSymbolAddress((void**)&hf,   g_hfood);
    cudaGetSymbolAddress((void**)&hn,   g_hnut);
    cudaGetSymbolAddress((void**)&as0,  g_as0);
    cudaGetSymbolAddress((void**)&as1,  g_as1);
    cudaGetSymbolAddress((void**)&ad0,  g_ad0);
    cudaGetSymbolAddress((void**)&ad1,  g_ad1);
    cudaGetSymbolAddress((void**)&Ad0,  g_Ad0);
    cudaGetSymbolAddress((void**)&Ad1,  g_Ad1);
    cudaGetSymbolAddress((void**)&off0, g_off0);
    cudaGetSymbolAddress((void**)&off1, g_off1);
    cudaGetSymbolAddress((void**)&cur0, g_cur0);
    cudaGetSymbolAddress((void**)&cur1, g_cur1);
    cudaGetSymbolAddress((void**)&csr0, g_csr0);
    cudaGetSymbolAddress((void**)&csr1, g_csr1);

    int gblocks = (NN + 127) / 128;
    int ablocks = (NN * 32 + 255) / 256;
    int aggblocks = (2 * NN * 32 + 255) / 256;

    // launch order keeps the ncu-profiled index-3 launch = gemm_fused
    avec2<<<2, 128>>>(Wdst_fn, Wdst_nf, att_dst_fn, att_dst_nf, Ad0, Ad1);   // 0
    zero2<<<196, 256>>>(off0, off1, NN + 1);                                  // 1
    hist2<<<512, 256>>>(ei_fn + EE, ei_nf + EE, off0, off1, EE);              // 2
    gemm_fused<<<dim3(gblocks, 2), 256>>>(                                    // 3 (profiled)
        x_food, x_nut, Wsrc_fn, Wsrc_nf, att_src_fn, att_src_nf,
        hs0, hs1, as0, as1);
    // alpha_d: rel0 dst = nut, rel1 dst = food
    alpha2<<<dim3(ablocks, 2), 256>>>(x_nut, x_food, Ad0, Ad1, ad0, ad1);     // 4
    scan2<<<2, 1024>>>(off0, off1, NN + 1);                                   // 5
    copy2<<<196, 256>>>(off0, off1, cur0, cur1, NN);                          // 6
    fill2<<<512, 256>>>(ei_fn, ei_nf, cur0, cur1, csr0, csr1, EE);            // 7
    gat_aggregate2<<<aggblocks, 256>>>(                                       // 8
        (const __half2*)hs0, as0, ad0, off0, csr0, bias_fn, hn,
        (const __half2*)hs1, as1, ad1, off1, csr1, bias_nf, hf);

    // layer 2
    avec2<<<2, 128>>>(Wdst_fn + DD * DD, Wdst_nf + DD * DD,
                      att_dst_fn + DD, att_dst_nf + DD, Ad0, Ad1);            // 9
    gemm_fused<<<dim3(gblocks, 2), 256>>>(                                    // 10
        hf, hn, Wsrc_fn + DD * DD, Wsrc_nf + DD * DD,
        att_src_fn + DD, att_src_nf + DD, hs0, hs1, as0, as1);
    alpha2<<<dim3(ablocks, 2), 256>>>(hn, hf, Ad0, Ad1, ad0, ad1);            // 11
    gat_aggregate2<<<aggblocks, 256>>>(                                       // 12
        (const __half2*)hs0, as0, ad0, off0, csr0, bias_fn + DD,
        out + (size_t)NN * DD,
        (const __half2*)hs1, as1, ad1, off1, csr1, bias_nf + DD, out);
}